// round 17
// baseline (speedup 1.0000x reference)
#include <cuda_runtime.h>

// 15x15 separable Gaussian, 8192x8192 f32, reflect pad, stride 1.
// Fused separable conv (R11 phase-2 + wide-tile phase-1):
//   Tile TX=240 x TY=60, 2 y-groups of 30 rows (128 threads x float2 = 256
//   vbuf cols). Phase-1 row-load amplification 44/30 = 1.47 (vs 1.7 at
//   TY=80/4 groups); x-halo amp 256/240 = 1.067.
//   phase 1: vertical, packed f32x2 symmetric taps, register sliding window,
//            global -> smem vbuf. 30 steps = dynamic loop over 2 chunks x
//            15 unrolled steps (window rotation has period 15 -> small I$).
//            Interior CTAs use a bumped row pointer; border CTAs use refl.
//   phase 2: horizontal, 8-output runs, FFMA-imm, row-pair interleaved map,
//            conflict-free LDS.128 (VSTRIDE=260 -> row stride == 16 mod 128).
// Coefficients hardcoded (problem-fixed Gaussian sigma=3, 15 taps);
// rel_err ~2.4e-7 verified across rounds.

#define IMW 8192
#define IMH 8192
#define TX  240          // output tile width (256 vbuf cols incl. 8+8 halo)
#define TY  60           // output tile height (2 groups x 30 rows)
#define VSTRIDE 260      // floats; 260*4=1040 B, 1040 % 128 == 16
#define NSX 35           // ceil(8192/240)
#define NSY 137          // ceil(8192/60)
#define SMEM_BYTES (TY * VSTRIDE * 4)   // 62400

static __device__ __forceinline__ int refl(int i) {
    i = (i < 0) ? -i : i;
    return (i >= IMW) ? (2 * IMW - 2 - i) : i;
}

__device__ __forceinline__ float2 ffma2(float2 a, float2 b, float2 c) {
    unsigned long long ua = *reinterpret_cast<unsigned long long*>(&a);
    unsigned long long ub = *reinterpret_cast<unsigned long long*>(&b);
    unsigned long long uc = *reinterpret_cast<unsigned long long*>(&c);
    unsigned long long ud;
    asm("fma.rn.f32x2 %0, %1, %2, %3;" : "=l"(ud) : "l"(ua), "l"(ub), "l"(uc));
    return *reinterpret_cast<float2*>(&ud);
}

__device__ __forceinline__ float2 fmul2(float2 a, float2 b) {
    unsigned long long ua = *reinterpret_cast<unsigned long long*>(&a);
    unsigned long long ub = *reinterpret_cast<unsigned long long*>(&b);
    unsigned long long ud;
    asm("mul.rn.f32x2 %0, %1, %2;" : "=l"(ud) : "l"(ua), "l"(ub));
    return *reinterpret_cast<float2*>(&ud);
}

__device__ __forceinline__ float2 fadd2(float2 a, float2 b) {
    unsigned long long ua = *reinterpret_cast<unsigned long long*>(&a);
    unsigned long long ub = *reinterpret_cast<unsigned long long*>(&b);
    unsigned long long ud;
    asm("add.rn.f32x2 %0, %1, %2;" : "=l"(ud) : "l"(ua), "l"(ub));
    return *reinterpret_cast<float2*>(&ud);
}

__global__ __launch_bounds__(256, 3)
void gauss_sep_kernel(const float* __restrict__ img,
                      float* __restrict__ out) {
    // normalized 1-D Gaussian, sigma=3, 15 taps (fp32)
    const float KC[15] = {
        0.00884695f, 0.01821590f, 0.03356240f, 0.05533503f,
        0.08163801f, 0.10777792f, 0.12732457f, 0.13459834f,
        0.12732457f, 0.10777792f, 0.08163801f, 0.05533503f,
        0.03356240f, 0.01821590f, 0.00884695f };

    extern __shared__ __align__(16) float vbuf[];   // TY * VSTRIDE floats

    const int tid = threadIdx.x;
    const int bx = blockIdx.x;
    const int by = blockIdx.y;

    // ---- phase 1: vertical conv (packed f32x2, symmetric), global -> vbuf ----
    {
        const int pc = tid & 127;       // float2 column 0..127 (256 vbuf cols)
        const int g  = tid >> 7;        // y-group 0..1 (30 vbuf rows each)
        const int gxp = bx * TX - 8 + 2 * pc;          // global col of pair
        const int gy0 = by * TY + 30 * g;              // first output row of group

        float2 kyv[8];
        #pragma unroll
        for (int i = 0; i < 8; i++) kyv[i] = make_float2(KC[i], KC[i]);

        float2 win[15];

        const bool interior = (bx > 0) && (bx < NSX - 1) && (by > 0) && (by < NSY - 1);

        if (interior) {
            // fast path: no reflection anywhere; bumped row pointer
            const float* rp = img + (size_t)(gy0 - 7) * IMW + gxp;
            #pragma unroll
            for (int i = 0; i < 14; i++) {
                win[i] = *reinterpret_cast<const float2*>(rp);
                rp += IMW;
            }
            for (int chunk = 0; chunk < 2; chunk++) {
                float* vrow = &vbuf[(30 * g + 15 * chunk) * VSTRIDE + 2 * pc];
                #pragma unroll
                for (int b = 0; b < 15; b++) {
                    const float2 nv = *reinterpret_cast<const float2*>(rp);
                    rp += IMW;
                    win[(14 + b) % 15] = nv;

                    float2 acc = fmul2(kyv[7], win[(b + 7) % 15]);
                    #pragma unroll
                    for (int i = 0; i < 7; i++)
                        acc = ffma2(kyv[i],
                                    fadd2(win[(b + i) % 15], win[(b + 14 - i) % 15]),
                                    acc);

                    *reinterpret_cast<float2*>(vrow) = acc;
                    vrow += VSTRIDE;
                }
            }
        } else {
            const bool xok = (gxp >= 0) && (gxp + 1 < IMW);
            const int rx0 = refl(gxp);
            const int rx1 = refl(gxp + 1);

            #pragma unroll
            for (int i = 0; i < 14; i++) {
                const int ry = refl(gy0 - 7 + i);
                const float* rp = img + (size_t)ry * IMW;
                if (xok) {
                    win[i] = *reinterpret_cast<const float2*>(rp + gxp);
                } else {
                    win[i].x = rp[rx0]; win[i].y = rp[rx1];
                }
            }
            for (int chunk = 0; chunk < 2; chunk++) {
                float* vrow = &vbuf[(30 * g + 15 * chunk) * VSTRIDE + 2 * pc];
                #pragma unroll
                for (int b = 0; b < 15; b++) {
                    const int s = 15 * chunk + b;
                    const int ry = refl(gy0 + s + 7);
                    const float* rp = img + (size_t)ry * IMW;
                    float2 nv;
                    if (xok) {
                        nv = *reinterpret_cast<const float2*>(rp + gxp);
                    } else {
                        nv.x = rp[rx0]; nv.y = rp[rx1];
                    }
                    win[(14 + b) % 15] = nv;

                    float2 acc = fmul2(kyv[7], win[(b + 7) % 15]);
                    #pragma unroll
                    for (int i = 0; i < 7; i++)
                        acc = ffma2(kyv[i],
                                    fadd2(win[(b + i) % 15], win[(b + 14 - i) % 15]),
                                    acc);

                    *reinterpret_cast<float2*>(vrow) = acc;
                    vrow += VSTRIDE;
                }
            }
        }
    }
    __syncthreads();

    // ---- phase 2: horizontal conv, 8-output runs, FFMA-imm, vbuf -> out ----
    // 30 runs/row * 60 rows = 1800 tasks. Row-pair interleave: each 8-lane
    // LDS.128 phase hits addresses {0,16,...,112} (+32*q0) mod 128.
    {
        const int X0  = bx * TX;
        const int gyb = by * TY;

        for (int t = tid; t < 1800; t += 256) {
            const int r2  = t / 60;
            const int u   = t - r2 * 60;
            const int row = 2 * r2 + (u & 1);
            const int q   = u >> 1;              // run 0..29

            const float* vp = &vbuf[row * VSTRIDE + q * 8];
            float w[24];
            #pragma unroll
            for (int j = 0; j < 6; j++) {
                const float4 f = *reinterpret_cast<const float4*>(vp + 4 * j);
                w[4 * j]     = f.x;
                w[4 * j + 1] = f.y;
                w[4 * j + 2] = f.z;
                w[4 * j + 3] = f.w;
            }

            // output k (0..7) at tile col q*8+k uses w[1+k .. 15+k]
            float o[8];
            #pragma unroll
            for (int k = 0; k < 8; k++) o[k] = KC[0] * w[1 + k];
            #pragma unroll
            for (int i = 1; i < 15; i++) {
                #pragma unroll
                for (int k = 0; k < 8; k++)
                    o[k] = fmaf(KC[i], w[1 + k + i], o[k]);
            }

            const int gy = gyb + row;
            const int gx = X0 + 8 * q;
            if (gy < IMH && gx + 7 < IMW) {
                float* op = out + (size_t)gy * IMW + gx;
                *reinterpret_cast<float4*>(op) =
                    make_float4(o[0], o[1], o[2], o[3]);
                *reinterpret_cast<float4*>(op + 4) =
                    make_float4(o[4], o[5], o[6], o[7]);
            }
        }
    }
}

extern "C" void kernel_launch(void* const* d_in, const int* in_sizes, int n_in,
                              void* d_out, int out_size) {
    const float* img = (const float*)d_in[0];
    float* out = (float*)d_out;

    static bool attr_set = false;
    if (!attr_set) {
        cudaFuncSetAttribute(gauss_sep_kernel,
                             cudaFuncAttributeMaxDynamicSharedMemorySize,
                             SMEM_BYTES);
        attr_set = true;
    }

    dim3 grid(NSX, NSY);
    gauss_sep_kernel<<<grid, 256, SMEM_BYTES>>>(img, out);
}